// round 1
// baseline (speedup 1.0000x reference)
#include <cuda_runtime.h>
#include <math.h>

// Problem constants: B=32, C=512, H=W=32, HW=1024, OUT=256
#define EPSV 1e-5f

// Scratch (allocation-free rule: device globals)
__device__ float g_tp[16384 * 512];   // [b*512+c][o'] : o'<256 theta, o'>=256 phi  (32 MB)
__device__ float g_xe[16384];         // [b*512+o] sum of relu(bn3) over 1024 pixels
__device__ float g_u[8192];           // [b*256+k]
__device__ float g_v[8192];           // [b*256+k]

// ---------- packed f32x2 helpers ----------
__device__ __forceinline__ unsigned long long pack2(float a, float b) {
    unsigned long long r;
    asm("mov.b64 %0, {%1,%2};" : "=l"(r) : "f"(a), "f"(b));
    return r;
}
__device__ __forceinline__ float2 unpack2(unsigned long long v) {
    float2 r;
    asm("mov.b64 {%0,%1}, %2;" : "=f"(r.x), "=f"(r.y) : "l"(v));
    return r;
}
__device__ __forceinline__ void fma2(unsigned long long& d, unsigned long long a, unsigned long long b) {
    asm("fma.rn.f32x2 %0, %1, %2, %0;" : "+l"(d) : "l"(a), "l"(b));
}

// ---------- zero scratch accumulators ----------
__global__ void k_zero() {
    int i = blockIdx.x * 256 + threadIdx.x;   // 64 blocks * 256 = 16384
    if (i < 16384) g_xe[i] = 0.f;
    if (i < 8192) { g_u[i] = 0.f; g_v[i] = 0.f; }
}

// ---------- GEMM1: TP[m][n] = relu(bn( X[m,:] . Wcat[n,:] )) ----------
// M=16384 (b*c), K=1024, N=512 (n<256 -> w1/bn1, n>=256 -> w2/bn2)
__global__ void __launch_bounds__(256, 2) k_gemm1(
    const float* __restrict__ X,
    const float* __restrict__ W1, const float* __restrict__ W2,
    const float* __restrict__ B1, const float* __restrict__ G1, const float* __restrict__ BE1,
    const float* __restrict__ Mu1, const float* __restrict__ Va1,
    const float* __restrict__ B2, const float* __restrict__ G2, const float* __restrict__ BE2,
    const float* __restrict__ Mu2, const float* __restrict__ Va2)
{
    __shared__ float As[8][132];
    __shared__ float Bs[8][132];

    const int tid = threadIdx.x;
    const int tx = tid & 15, ty = tid >> 4;
    const int lrow = tid >> 1, lk = (tid & 1) * 4;

    const float* aptr = X + (size_t)(blockIdx.x * 128 + lrow) * 1024 + lk;
    const int ncol = blockIdx.y * 128 + lrow;
    const float* bptr = (ncol < 256 ? W1 + (size_t)ncol * 1024
                                    : W2 + (size_t)(ncol - 256) * 1024) + lk;

    unsigned long long acc[8][4];
#pragma unroll
    for (int i = 0; i < 8; i++)
#pragma unroll
        for (int j = 0; j < 4; j++) acc[i][j] = 0ULL;

    for (int k0 = 0; k0 < 1024; k0 += 8) {
        float4 a4 = *(const float4*)aptr; aptr += 8;
        float4 b4 = *(const float4*)bptr; bptr += 8;
        __syncthreads();
        As[lk + 0][lrow] = a4.x; As[lk + 1][lrow] = a4.y;
        As[lk + 2][lrow] = a4.z; As[lk + 3][lrow] = a4.w;
        Bs[lk + 0][lrow] = b4.x; Bs[lk + 1][lrow] = b4.y;
        Bs[lk + 2][lrow] = b4.z; Bs[lk + 3][lrow] = b4.w;
        __syncthreads();
#pragma unroll
        for (int k = 0; k < 8; k++) {
            float4 ra0 = *(const float4*)&As[k][ty * 8];
            float4 ra1 = *(const float4*)&As[k][ty * 8 + 4];
            const unsigned long long* brow = (const unsigned long long*)&Bs[k][tx * 8];
            unsigned long long b0 = brow[0], b1 = brow[1], b2 = brow[2], b3 = brow[3];
            float a_[8] = {ra0.x, ra0.y, ra0.z, ra0.w, ra1.x, ra1.y, ra1.z, ra1.w};
#pragma unroll
            for (int i = 0; i < 8; i++) {
                unsigned long long pa = pack2(a_[i], a_[i]);
                fma2(acc[i][0], pa, b0);
                fma2(acc[i][1], pa, b1);
                fma2(acc[i][2], pa, b2);
                fma2(acc[i][3], pa, b3);
            }
        }
    }

    // epilogue: bias + BN + relu, per column
    const int row0 = blockIdx.x * 128 + ty * 8;
    const int col0 = blockIdx.y * 128 + tx * 8;
    float alpha[8], beta[8];
#pragma unroll
    for (int j = 0; j < 8; j++) {
        int n = col0 + j;
        float bb, gg, bee, mm, vv;
        if (n < 256) { bb = B1[n]; gg = G1[n]; bee = BE1[n]; mm = Mu1[n]; vv = Va1[n]; }
        else { int o = n - 256; bb = B2[o]; gg = G2[o]; bee = BE2[o]; mm = Mu2[o]; vv = Va2[o]; }
        float a = gg * rsqrtf(vv + EPSV);
        alpha[j] = a;
        beta[j] = (bb - mm) * a + bee;
    }
#pragma unroll
    for (int i = 0; i < 8; i++) {
        float vals[8];
#pragma unroll
        for (int j4 = 0; j4 < 4; j4++) {
            float2 f = unpack2(acc[i][j4]);
            vals[2 * j4] = f.x; vals[2 * j4 + 1] = f.y;
        }
        float4 o0, o1;
        o0.x = fmaxf(fmaf(vals[0], alpha[0], beta[0]), 0.f);
        o0.y = fmaxf(fmaf(vals[1], alpha[1], beta[1]), 0.f);
        o0.z = fmaxf(fmaf(vals[2], alpha[2], beta[2]), 0.f);
        o0.w = fmaxf(fmaf(vals[3], alpha[3], beta[3]), 0.f);
        o1.x = fmaxf(fmaf(vals[4], alpha[4], beta[4]), 0.f);
        o1.y = fmaxf(fmaf(vals[5], alpha[5], beta[5]), 0.f);
        o1.z = fmaxf(fmaf(vals[6], alpha[6], beta[6]), 0.f);
        o1.w = fmaxf(fmaf(vals[7], alpha[7], beta[7]), 0.f);
        *(float4*)&g_tp[(size_t)(row0 + i) * 512 + col0] = o0;
        *(float4*)&g_tp[(size_t)(row0 + i) * 512 + col0 + 4] = o1;
    }
}

// ---------- GEMM2: xe_sum[b,o] += sum_p relu(bn3( W3[o,:] . X[b,:,p] )) ----------
// per batch: [512 o x 1024 p], K=512; fused ReLU+sum epilogue (no 64MB intermediate)
__global__ void __launch_bounds__(256, 2) k_gemm2(
    const float* __restrict__ X, const float* __restrict__ W3,
    const float* __restrict__ B3, const float* __restrict__ G3, const float* __restrict__ BE3,
    const float* __restrict__ Mu3, const float* __restrict__ Va3)
{
    __shared__ float As[8][132];
    __shared__ float Bs[8][132];
    __shared__ float red[128][17];

    const int tid = threadIdx.x;
    const int pt = blockIdx.x;   // 0..7
    const int ot = blockIdx.y;   // 0..3
    const int b  = blockIdx.z;   // 0..31
    const int tx = tid & 15, ty = tid >> 4;
    const int lrow = tid >> 1, lk = (tid & 1) * 4;   // A (w3) load
    const int krow = tid >> 5, pc4 = (tid & 31) * 4; // B (x) load

    const float* aptr = W3 + (size_t)(ot * 128 + lrow) * 512 + lk;
    const float* bptr = X + ((size_t)b * 512 + krow) * 1024 + pt * 128 + pc4;

    unsigned long long acc[8][4];
#pragma unroll
    for (int i = 0; i < 8; i++)
#pragma unroll
        for (int j = 0; j < 4; j++) acc[i][j] = 0ULL;

    for (int k0 = 0; k0 < 512; k0 += 8) {
        float4 a4 = *(const float4*)aptr; aptr += 8;
        float4 b4 = *(const float4*)bptr; bptr += (size_t)8 * 1024;
        __syncthreads();
        As[lk + 0][lrow] = a4.x; As[lk + 1][lrow] = a4.y;
        As[lk + 2][lrow] = a4.z; As[lk + 3][lrow] = a4.w;
        *(float4*)&Bs[krow][pc4] = b4;
        __syncthreads();
#pragma unroll
        for (int k = 0; k < 8; k++) {
            float4 ra0 = *(const float4*)&As[k][ty * 8];
            float4 ra1 = *(const float4*)&As[k][ty * 8 + 4];
            const unsigned long long* brow = (const unsigned long long*)&Bs[k][tx * 8];
            unsigned long long b0 = brow[0], b1 = brow[1], b2 = brow[2], b3 = brow[3];
            float a_[8] = {ra0.x, ra0.y, ra0.z, ra0.w, ra1.x, ra1.y, ra1.z, ra1.w};
#pragma unroll
            for (int i = 0; i < 8; i++) {
                unsigned long long pa = pack2(a_[i], a_[i]);
                fma2(acc[i][0], pa, b0);
                fma2(acc[i][1], pa, b1);
                fma2(acc[i][2], pa, b2);
                fma2(acc[i][3], pa, b3);
            }
        }
    }

    // epilogue: per-o BN+relu, sum over this block's 8 p values per thread
    const int o0 = ot * 128;
    float rowsum[8];
#pragma unroll
    for (int i = 0; i < 8; i++) {
        int o = o0 + ty * 8 + i;
        float a = G3[o] * rsqrtf(Va3[o] + EPSV);
        float be = (B3[o] - Mu3[o]) * a + BE3[o];
        float s = 0.f;
#pragma unroll
        for (int j4 = 0; j4 < 4; j4++) {
            float2 f = unpack2(acc[i][j4]);
            s += fmaxf(fmaf(f.x, a, be), 0.f) + fmaxf(fmaf(f.y, a, be), 0.f);
        }
        rowsum[i] = s;
    }
#pragma unroll
    for (int i = 0; i < 8; i++) red[ty * 8 + i][tx] = rowsum[i];
    __syncthreads();
    if (tid < 128) {
        float s = 0.f;
#pragma unroll
        for (int t = 0; t < 16; t++) s += red[tid][t];
        atomicAdd(&g_xe[b * 512 + o0 + tid], s);
    }
}

// ---------- u/v contractions (collapse affinity GEMM) ----------
// u[b,k] = sum_i w4a[i]*phi_s[b][i][k] ; v[b,k] = sum_i w4b[i]*theta_s[b][i][k]
__global__ void __launch_bounds__(256) k_uv(const float* __restrict__ w4) {
    const int b = blockIdx.x;        // 0..31
    const int ch = blockIdx.y;       // 0..7 -> 64 i's each
    const int k = threadIdx.x;       // 0..255
    __shared__ float wa[64], wb[64];
    if (k < 64) { wa[k] = w4[1 + ch * 64 + k]; wb[k] = w4[513 + ch * 64 + k]; }
    __syncthreads();
    const float* base = g_tp + (size_t)b * 512 * 512 + (size_t)ch * 64 * 512;
    float u = 0.f, v = 0.f;
#pragma unroll 4
    for (int i = 0; i < 64; i++) {
        float th = base[i * 512 + k];
        float ph = base[i * 512 + 256 + k];
        u = fmaf(wa[i], ph, u);
        v = fmaf(wb[i], th, v);
    }
    atomicAdd(&g_u[b * 256 + k], u);
    atomicAdd(&g_v[b * 256 + k], v);
}

// ---------- final: logits, sigmoid, gate ----------
__global__ void __launch_bounds__(256) k_final(
    const float* __restrict__ X, const float* __restrict__ w4,
    const float* __restrict__ b4, float* __restrict__ OUT)
{
    const int m = blockIdx.x;        // 0..16383 = b*512 + p(channel)
    const int b = m >> 9;
    const int tid = threadIdx.x;     // 256 = k
    __shared__ float sred[8];
    __shared__ float s_a;

    float th = g_tp[(size_t)m * 512 + tid];
    float ph = g_tp[(size_t)m * 512 + 256 + tid];
    float partial = g_u[b * 256 + tid] * th + g_v[b * 256 + tid] * ph;
#pragma unroll
    for (int o = 16; o; o >>= 1) partial += __shfl_xor_sync(0xffffffff, partial, o);
    if ((tid & 31) == 0) sred[tid >> 5] = partial;
    __syncthreads();
    if (tid == 0) {
        float tot = 0.f;
#pragma unroll
        for (int w = 0; w < 8; w++) tot += sred[w];
        float xe = g_xe[m] * (1.f / 1024.f);
        float logit = w4[0] * xe + tot + b4[0];
        s_a = 1.f / (1.f + expf(-logit));
    }
    __syncthreads();
    float a = s_a;
    const float4* xin = (const float4*)(X + (size_t)m * 1024);
    float4* xo = (float4*)(OUT + (size_t)m * 1024);
    float4 v = xin[tid];
    v.x *= a; v.y *= a; v.z *= a; v.w *= a;
    xo[tid] = v;
}

extern "C" void kernel_launch(void* const* d_in, const int* in_sizes, int n_in,
                              void* d_out, int out_size) {
    const float* x   = (const float*)d_in[0];
    const float* w1  = (const float*)d_in[1];
    const float* b1  = (const float*)d_in[2];
    const float* g1  = (const float*)d_in[3];
    const float* be1 = (const float*)d_in[4];
    const float* m1  = (const float*)d_in[5];
    const float* v1  = (const float*)d_in[6];
    const float* w2  = (const float*)d_in[7];
    const float* b2  = (const float*)d_in[8];
    const float* g2  = (const float*)d_in[9];
    const float* be2 = (const float*)d_in[10];
    const float* m2  = (const float*)d_in[11];
    const float* v2  = (const float*)d_in[12];
    const float* w3  = (const float*)d_in[13];
    const float* b3  = (const float*)d_in[14];
    const float* g3  = (const float*)d_in[15];
    const float* be3 = (const float*)d_in[16];
    const float* m3  = (const float*)d_in[17];
    const float* v3  = (const float*)d_in[18];
    const float* w4  = (const float*)d_in[19];
    const float* b4  = (const float*)d_in[20];
    float* out = (float*)d_out;

    k_zero<<<64, 256>>>();
    dim3 grid1(128, 4);
    k_gemm1<<<grid1, 256>>>(x, w1, w2, b1, g1, be1, m1, v1, b2, g2, be2, m2, v2);
    dim3 grid2(8, 4, 32);
    k_gemm2<<<grid2, 256>>>(x, w3, b3, g3, be3, m3, v3);
    dim3 grid3(32, 8);
    k_uv<<<grid3, 256>>>(w4);
    k_final<<<16384, 256>>>(x, w4, b4, out);
}

// round 3
// speedup vs baseline: 2.3025x; 2.3025x over previous
#include <cuda_runtime.h>
#include <cuda_fp16.h>
#include <cstdint>
#include <math.h>

#define EPSV 1e-5f

// ---------------- scratch (device globals; no allocs allowed) ----------------
__device__ float g_tp[16384 * 512];        // 32 MB: [b*512+c][n] n<256 theta, n>=256 phi
__device__ float g_xt[32 * 1024 * 512];    // 64 MB: X transposed -> [b][p][c]
__device__ float g_xe[16384];              // [b*512+o] sum over 1024 pixels
__device__ float g_u[8192];
__device__ float g_v[8192];

__device__ __forceinline__ uint32_t smem_u32(const void* p) {
    uint32_t a;
    asm("{ .reg .u64 t; cvta.to.shared.u64 t, %1; cvt.u32.u64 %0, t; }" : "=r"(a) : "l"(p));
    return a;
}

#define LDSM4(R, addr) \
    asm volatile("ldmatrix.sync.aligned.m8n8.x4.shared.b16 {%0,%1,%2,%3}, [%4];" \
                 : "=r"((R)[0]), "=r"((R)[1]), "=r"((R)[2]), "=r"((R)[3]) : "r"(addr))

#define MMA(D, A, b0, b1) \
    asm volatile("mma.sync.aligned.m16n8k16.row.col.f32.f16.f16.f32 " \
                 "{%0,%1,%2,%3},{%4,%5,%6,%7},{%8,%9},{%0,%1,%2,%3};" \
                 : "+f"((D)[0]), "+f"((D)[1]), "+f"((D)[2]), "+f"((D)[3]) \
                 : "r"((A)[0]), "r"((A)[1]), "r"((A)[2]), "r"((A)[3]), "r"(b0), "r"(b1))

__device__ __forceinline__ void sts_v2(uint32_t addr, uint32_t a, uint32_t b) {
    asm volatile("st.shared.v2.u32 [%0], {%1,%2};" :: "r"(addr), "r"(a), "r"(b) : "memory");
}

// fp32x4 -> fp16 hi pair + fp16 residual pair
__device__ __forceinline__ void split4h(float4 v, uint32_t& h01, uint32_t& h23,
                                        uint32_t& l01, uint32_t& l23) {
    __half2 h0 = __floats2half2_rn(v.x, v.y);
    __half2 h1 = __floats2half2_rn(v.z, v.w);
    float2 f0 = __half22float2(h0);
    float2 f1 = __half22float2(h1);
    __half2 l0 = __floats2half2_rn(v.x - f0.x, v.y - f0.y);
    __half2 l1 = __floats2half2_rn(v.z - f1.x, v.w - f1.y);
    h01 = *(uint32_t*)&h0; h23 = *(uint32_t*)&h1;
    l01 = *(uint32_t*)&l0; l23 = *(uint32_t*)&l1;
}

// ---------------- shared mainloop ----------------
// D[128x128] += A[128xK] . B[128xK]^T, fp32 via fp16 hi/lo 3-term split.
// smem: Ahi, Alo, Bhi, Blo : 128 rows x 40 halfs (80B rows, padded)
template <int NCH>
__device__ __forceinline__ void run_mainloop(
    const float* gA, int ldA, const float* gB, int ldB,
    char* sm, int tid, float acc[2][8][4])
{
    const int lane = tid & 31, w = tid >> 5;
    const int wm = (w & 3) * 32, wn = (w >> 2) * 64;
    const uint32_t sbase = smem_u32(sm);
    const uint32_t sAhi = sbase, sAlo = sbase + 10240;
    const uint32_t sBhi = sbase + 20480, sBlo = sbase + 30720;
    const int lr = tid >> 3;                 // 0..31
    const int lc = (tid & 7) * 4;            // f32 col within chunk
    const uint32_t stoff = (uint32_t)lr * 80 + (uint32_t)(tid & 7) * 8;
    const uint32_t aRow = (uint32_t)(wm + (lane & 15)) * 80 + (uint32_t)(lane >> 4) * 16;
    const uint32_t bRow = (uint32_t)(wn + (lane & 7) + 8 * (lane >> 4)) * 80
                        + (uint32_t)((lane >> 3) & 1) * 16;

    float4 ra[4], rb[4];
#pragma unroll
    for (int i = 0; i < 4; i++) {
        ra[i] = *(const float4*)(gA + (size_t)(lr + i * 32) * ldA + lc);
        rb[i] = *(const float4*)(gB + (size_t)(lr + i * 32) * ldB + lc);
    }

    for (int c = 0; c < NCH; c++) {
        __syncthreads();
#pragma unroll
        for (int i = 0; i < 4; i++) {
            uint32_t o = stoff + i * 32 * 80;
            uint32_t h01, h23, l01, l23;
            split4h(ra[i], h01, h23, l01, l23);
            sts_v2(sAhi + o, h01, h23);
            sts_v2(sAlo + o, l01, l23);
            split4h(rb[i], h01, h23, l01, l23);
            sts_v2(sBhi + o, h01, h23);
            sts_v2(sBlo + o, l01, l23);
        }
        if (c + 1 < NCH) {
            const int kof = (c + 1) * 32 + lc;
#pragma unroll
            for (int i = 0; i < 4; i++) {
                ra[i] = *(const float4*)(gA + (size_t)(lr + i * 32) * ldA + kof);
                rb[i] = *(const float4*)(gB + (size_t)(lr + i * 32) * ldB + kof);
            }
        }
        __syncthreads();

#pragma unroll
        for (int k16 = 0; k16 < 2; k16++) {
            const uint32_t kb = k16 * 32;   // 16 halfs = 32B
            uint32_t ah[2][4], al[2][4], bb[4][4];
            LDSM4(ah[0], sAhi + aRow + kb);
            LDSM4(ah[1], sAhi + aRow + 1280 + kb);
            LDSM4(al[0], sAlo + aRow + kb);
            LDSM4(al[1], sAlo + aRow + 1280 + kb);
#pragma unroll
            for (int p = 0; p < 4; p++) LDSM4(bb[p], sBhi + bRow + p * 1280 + kb);
#pragma unroll
            for (int mt = 0; mt < 2; mt++)
#pragma unroll
                for (int nt = 0; nt < 8; nt++) {
                    uint32_t b0 = bb[nt >> 1][(nt & 1) * 2];
                    uint32_t b1 = bb[nt >> 1][(nt & 1) * 2 + 1];
                    MMA(acc[mt][nt], ah[mt], b0, b1);   // hi*hi
                    MMA(acc[mt][nt], al[mt], b0, b1);   // lo*hi
                }
#pragma unroll
            for (int p = 0; p < 4; p++) LDSM4(bb[p], sBlo + bRow + p * 1280 + kb);
#pragma unroll
            for (int mt = 0; mt < 2; mt++)
#pragma unroll
                for (int nt = 0; nt < 8; nt++) {
                    uint32_t b0 = bb[nt >> 1][(nt & 1) * 2];
                    uint32_t b1 = bb[nt >> 1][(nt & 1) * 2 + 1];
                    MMA(acc[mt][nt], ah[mt], b0, b1);   // hi*lo
                }
        }
    }
}

// ---------------- GEMM1: g_tp[m][n] = relu(bn(X[m,:] . Wcat[n,:])) ----------------
__global__ void __launch_bounds__(256, 1) k_gemm1(
    const float* __restrict__ X,
    const float* __restrict__ W1, const float* __restrict__ W2,
    const float* __restrict__ B1, const float* __restrict__ G1, const float* __restrict__ BE1,
    const float* __restrict__ Mu1, const float* __restrict__ Va1,
    const float* __restrict__ B2, const float* __restrict__ G2, const float* __restrict__ BE2,
    const float* __restrict__ Mu2, const float* __restrict__ Va2)
{
    __shared__ char sm[40960];
    __shared__ float s_al[128], s_be[128];

    const int tid = threadIdx.x;
    const int n0 = blockIdx.y * 128;
    const int m0 = blockIdx.x * 128;

    if (tid < 128) {
        int n = n0 + tid;
        float bb, gg, bee, mm, vv;
        if (n < 256) { bb = B1[n]; gg = G1[n]; bee = BE1[n]; mm = Mu1[n]; vv = Va1[n]; }
        else { int o = n - 256; bb = B2[o]; gg = G2[o]; bee = BE2[o]; mm = Mu2[o]; vv = Va2[o]; }
        float a = gg * rsqrtf(vv + EPSV);
        s_al[tid] = a;
        s_be[tid] = (bb - mm) * a + bee;
    }

    const float* Wb = (blockIdx.y < 2) ? (W1 + (size_t)n0 * 1024)
                                       : (W2 + (size_t)(n0 - 256) * 1024);
    const float* gA = X + (size_t)m0 * 1024;

    float acc[2][8][4];
#pragma unroll
    for (int mt = 0; mt < 2; mt++)
#pragma unroll
        for (int nt = 0; nt < 8; nt++)
#pragma unroll
            for (int j = 0; j < 4; j++) acc[mt][nt][j] = 0.f;

    run_mainloop<32>(gA, 1024, Wb, 1024, sm, tid, acc);

    // epilogue: BN + relu -> g_tp
    const int lane = tid & 31, w = tid >> 5;
    const int wm = (w & 3) * 32, wn = (w >> 2) * 64;
#pragma unroll
    for (int mt = 0; mt < 2; mt++) {
        int m = m0 + wm + mt * 16 + (lane >> 2);
#pragma unroll
        for (int nt = 0; nt < 8; nt++) {
            int nb = wn + nt * 8 + 2 * (lane & 3);
            float a0 = s_al[nb], a1 = s_al[nb + 1];
            float b0 = s_be[nb], b1 = s_be[nb + 1];
            float2 v0, v1;
            v0.x = fmaxf(fmaf(acc[mt][nt][0], a0, b0), 0.f);
            v0.y = fmaxf(fmaf(acc[mt][nt][1], a1, b1), 0.f);
            v1.x = fmaxf(fmaf(acc[mt][nt][2], a0, b0), 0.f);
            v1.y = fmaxf(fmaf(acc[mt][nt][3], a1, b1), 0.f);
            *(float2*)&g_tp[(size_t)m * 512 + n0 + nb] = v0;
            *(float2*)&g_tp[(size_t)(m + 8) * 512 + n0 + nb] = v1;
        }
    }
}

// ---------------- GEMM2: g_xe[b,o] += sum_p relu(bn3(W3[o,:] . Xt[b,p,:])) ----------------
__global__ void __launch_bounds__(256, 1) k_gemm2(
    const float* __restrict__ W3,
    const float* __restrict__ B3, const float* __restrict__ G3, const float* __restrict__ BE3,
    const float* __restrict__ Mu3, const float* __restrict__ Va3)
{
    __shared__ char sm[40960];

    const int tid = threadIdx.x;
    const int p0 = blockIdx.x * 128;   // N tile (pixels)
    const int o0 = blockIdx.y * 128;   // M tile (channels)
    const int b  = blockIdx.z;

    const float* gA = W3 + (size_t)o0 * 512;
    const float* gB = g_xt + ((size_t)b * 1024 + p0) * 512;

    float acc[2][8][4];
#pragma unroll
    for (int mt = 0; mt < 2; mt++)
#pragma unroll
        for (int nt = 0; nt < 8; nt++)
#pragma unroll
            for (int j = 0; j < 4; j++) acc[mt][nt][j] = 0.f;

    run_mainloop<16>(gA, 512, gB, 512, sm, tid, acc);

    // epilogue: BN + relu + reduce over pixels -> atomic g_xe
    const int lane = tid & 31, w = tid >> 5;
    const int wm = (w & 3) * 32;
#pragma unroll
    for (int mt = 0; mt < 2; mt++) {
        int o = o0 + wm + mt * 16 + (lane >> 2);
        float al0 = G3[o] * rsqrtf(Va3[o] + EPSV);
        float be0 = (B3[o] - Mu3[o]) * al0 + BE3[o];
        float al1 = G3[o + 8] * rsqrtf(Va3[o + 8] + EPSV);
        float be1 = (B3[o + 8] - Mu3[o + 8]) * al1 + BE3[o + 8];
        float s0 = 0.f, s1 = 0.f;
#pragma unroll
        for (int nt = 0; nt < 8; nt++) {
            s0 += fmaxf(fmaf(acc[mt][nt][0], al0, be0), 0.f)
                + fmaxf(fmaf(acc[mt][nt][1], al0, be0), 0.f);
            s1 += fmaxf(fmaf(acc[mt][nt][2], al1, be1), 0.f)
                + fmaxf(fmaf(acc[mt][nt][3], al1, be1), 0.f);
        }
        s0 += __shfl_xor_sync(0xffffffff, s0, 1);
        s0 += __shfl_xor_sync(0xffffffff, s0, 2);
        s1 += __shfl_xor_sync(0xffffffff, s1, 1);
        s1 += __shfl_xor_sync(0xffffffff, s1, 2);
        if ((lane & 3) == 0) {
            atomicAdd(&g_xe[b * 512 + o], s0);
            atomicAdd(&g_xe[b * 512 + o + 8], s1);
        }
    }
}

// ---------------- transpose X[b][c][p] -> g_xt[b][p][c] ----------------
__global__ void __launch_bounds__(256) k_transpose(const float* __restrict__ X) {
    __shared__ float st[32][133];
    const int tid = threadIdx.x;
    const int p0 = blockIdx.x * 128;
    const int c0 = blockIdx.y * 32;
    const int b  = blockIdx.z;
#pragma unroll
    for (int pass = 0; pass < 4; pass++) {
        int ci = (tid >> 5) + pass * 8;
        int pj = (tid & 31) * 4;
        float4 v = *(const float4*)(X + ((size_t)b * 512 + c0 + ci) * 1024 + p0 + pj);
        st[ci][pj + 0] = v.x; st[ci][pj + 1] = v.y; st[ci][pj + 2] = v.z; st[ci][pj + 3] = v.w;
    }
    __syncthreads();
#pragma unroll
    for (int pass = 0; pass < 4; pass++) {
        int pi = (tid >> 3) + pass * 32;
        int cj = (tid & 7) * 4;
        float4 v;
        v.x = st[cj + 0][pi]; v.y = st[cj + 1][pi]; v.z = st[cj + 2][pi]; v.w = st[cj + 3][pi];
        *(float4*)(g_xt + ((size_t)b * 1024 + p0 + pi) * 512 + c0 + cj) = v;
    }
}

// ---------------- small kernels ----------------
__global__ void k_zero() {
    int i = blockIdx.x * 256 + threadIdx.x;
    if (i < 16384) g_xe[i] = 0.f;
    if (i < 8192) { g_u[i] = 0.f; g_v[i] = 0.f; }
}

__global__ void __launch_bounds__(256) k_uv(const float* __restrict__ w4) {
    const int b = blockIdx.x;
    const int ch = blockIdx.y;
    const int k = threadIdx.x;
    __shared__ float wa[64], wb[64];
    if (k < 64) { wa[k] = w4[1 + ch * 64 + k]; wb[k] = w4[513 + ch * 64 + k]; }
    __syncthreads();
    const float* base = g_tp + (size_t)b * 512 * 512 + (size_t)ch * 64 * 512;
    float u = 0.f, v = 0.f;
#pragma unroll 4
    for (int i = 0; i < 64; i++) {
        float th = base[i * 512 + k];
        float ph = base[i * 512 + 256 + k];
        u = fmaf(wa[i], ph, u);
        v = fmaf(wb[i], th, v);
    }
    atomicAdd(&g_u[b * 256 + k], u);
    atomicAdd(&g_v[b * 256 + k], v);
}

__global__ void __launch_bounds__(256) k_final(
    const float* __restrict__ X, const float* __restrict__ w4,
    const float* __restrict__ b4, float* __restrict__ OUT)
{
    const int m = blockIdx.x;
    const int b = m >> 9;
    const int tid = threadIdx.x;
    __shared__ float sred[8];
    __shared__ float s_a;

    float th = g_tp[(size_t)m * 512 + tid];
    float ph = g_tp[(size_t)m * 512 + 256 + tid];
    float partial = g_u[b * 256 + tid] * th + g_v[b * 256 + tid] * ph;
#pragma unroll
    for (int o = 16; o; o >>= 1) partial += __shfl_xor_sync(0xffffffff, partial, o);
    if ((tid & 31) == 0) sred[tid >> 5] = partial;
    __syncthreads();
    if (tid == 0) {
        float tot = 0.f;
#pragma unroll
        for (int w = 0; w < 8; w++) tot += sred[w];
        float xe = g_xe[m] * (1.f / 1024.f);
        float logit = w4[0] * xe + tot + b4[0];
        s_a = 1.f / (1.f + expf(-logit));
    }
    __syncthreads();
    float a = s_a;
    const float4* xin = (const float4*)(X + (size_t)m * 1024);
    float4* xo = (float4*)(OUT + (size_t)m * 1024);
    float4 v = xin[tid];
    v.x *= a; v.y *= a; v.z *= a; v.w *= a;
    xo[tid] = v;
}

// ---------------- launch ----------------
extern "C" void kernel_launch(void* const* d_in, const int* in_sizes, int n_in,
                              void* d_out, int out_size) {
    const float* x   = (const float*)d_in[0];
    const float* w1  = (const float*)d_in[1];
    const float* b1  = (const float*)d_in[2];
    const float* g1  = (const float*)d_in[3];
    const float* be1 = (const float*)d_in[4];
    const float* m1  = (const float*)d_in[5];
    const float* v1  = (const float*)d_in[6];
    const float* w2  = (const float*)d_in[7];
    const float* b2  = (const float*)d_in[8];
    const float* g2  = (const float*)d_in[9];
    const float* be2 = (const float*)d_in[10];
    const float* m2  = (const float*)d_in[11];
    const float* v2  = (const float*)d_in[12];
    const float* w3  = (const float*)d_in[13];
    const float* b3  = (const float*)d_in[14];
    const float* g3  = (const float*)d_in[15];
    const float* be3 = (const float*)d_in[16];
    const float* m3  = (const float*)d_in[17];
    const float* v3  = (const float*)d_in[18];
    const float* w4  = (const float*)d_in[19];
    const float* b4  = (const float*)d_in[20];
    float* out = (float*)d_out;

    k_zero<<<64, 256>>>();
    k_transpose<<<dim3(8, 16, 32), 256>>>(x);
    k_gemm1<<<dim3(128, 4), 256>>>(x, w1, w2, b1, g1, be1, m1, v1,
                                   b2, g2, be2, m2, v2);
    k_gemm2<<<dim3(8, 4, 32), 256>>>(w3, b3, g3, be3, m3, v3);
    k_uv<<<dim3(32, 8), 256>>>(w4);
    k_final<<<16384, 256>>>(x, w4, b4, out);
}